// round 9
// baseline (speedup 1.0000x reference)
#include <cuda_runtime.h>
#include <math.h>

#define NHEADS   16
#define HDIM     64
#define ROT      32
#define BS       8
#define CACHE    4096
#define DMODEL   1024
#define SPLITS   8
#define CHUNK    (CACHE / SPLITS)   // 512
#define NPAIRS   (BS * NHEADS)      // 128

// Scratch (device globals — no runtime allocation allowed)
__device__ float g_proj[3 * BS * DMODEL];            // qh, kh, vh (proj + bias)
__device__ float g_pl[NPAIRS * SPLITS];              // split partial sum-of-exp
__device__ float g_pacc[NPAIRS * SPLITS * HDIM];     // split partial weighted V
__device__ float g_attn[BS * DMODEL];

// ---------------------------------------------------------------------------
// GEMV core: 1024 threads = 32 warps; 4 warps per output column (each warp
// owns a 256-dim quarter).  Per thread: 2 weight LDG.128 issued FIRST, then
// 2 staging LDG.128 (one overlapped latency round), 16 LDS.128 + 64 FFMA,
// shfl tree, 4-partial smem combine.
// ---------------------------------------------------------------------------
__device__ __forceinline__ void gemv_block(
    const float* __restrict__ X,
    const float* __restrict__ W,
    const float* __restrict__ bias,
    float* __restrict__ Y,
    int obase)
{
    __shared__ __align__(16) float sx[BS * DMODEL];
    __shared__ float spart[32][BS];

    int tid  = threadIdx.x;
    int warp = tid >> 5, lane = tid & 31;
    int colw = warp >> 2, quar = warp & 3;
    int o    = obase + colw;

    const float4* W4 = (const float4*)(W + (size_t)o * DMODEL);
    const float4* x4 = (const float4*)sx;

    float4 wv[2];
    wv[0] = W4[quar * 64 + lane];
    wv[1] = W4[quar * 64 + 32 + lane];

    {
        const float4* g4 = (const float4*)X;
        float4* s4 = (float4*)sx;
        float4 st0 = g4[tid];
        float4 st1 = g4[tid + 1024];
        s4[tid] = st0;
        s4[tid + 1024] = st1;
    }
    __syncthreads();

    float acc[BS];
#pragma unroll
    for (int b = 0; b < BS; b++) acc[b] = 0.f;
#pragma unroll
    for (int it = 0; it < 2; it++) {
        int d4 = quar * 64 + it * 32 + lane;
#pragma unroll
        for (int b = 0; b < BS; b++) {
            float4 xv = x4[b * (DMODEL / 4) + d4];
            acc[b] += wv[it].x * xv.x + wv[it].y * xv.y + wv[it].z * xv.z + wv[it].w * xv.w;
        }
    }
#pragma unroll
    for (int off = 16; off; off >>= 1) {
#pragma unroll
        for (int b = 0; b < BS; b++)
            acc[b] += __shfl_xor_sync(0xffffffffu, acc[b], off);
    }
    if (lane == 0) {
#pragma unroll
        for (int b = 0; b < BS; b++) spart[warp][b] = acc[b];
    }
    __syncthreads();

    if (tid < 64) {
        int c = tid >> 3, b = tid & 7;
        int oc = obase + c;
        float v = spart[4 * c][b] + spart[4 * c + 1][b]
                + spart[4 * c + 2][b] + spart[4 * c + 3][b] + bias[oc];
        Y[b * DMODEL + oc] = v;
    }
}

// ---------------------------------------------------------------------------
// Kernel 1: fused QKV projection.  grid 384; blocks 0..127 -> Q, 128..255 ->
// K, 256..383 -> V (uniform p per block).
// ---------------------------------------------------------------------------
__global__ void __launch_bounds__(1024, 1)
proj_kernel(const float* __restrict__ q,
            const float* __restrict__ WQ, const float* __restrict__ bQ,
            const float* __restrict__ WK, const float* __restrict__ bK,
            const float* __restrict__ WV, const float* __restrict__ bV) {
    int w0 = blockIdx.x * 8;
    int p  = w0 >> 10;
    int o  = w0 & 1023;
    const float* W    = (p == 0) ? WQ : (p == 1) ? WK : WV;
    const float* bias = (p == 0) ? bQ : (p == 1) ? bK : bV;
    gemv_block(q, W, bias, g_proj + (size_t)p * BS * DMODEL, o);
}

// ---------------------------------------------------------------------------
// Kernel 2: flash-decode, split-K (unchanged — near HBM roofline).
// ---------------------------------------------------------------------------
__global__ void attn_kernel(const float* __restrict__ kc,
                            const float* __restrict__ vc) {
    int split = blockIdx.x;
    int pair  = blockIdx.y;
    int b = pair >> 4, h = pair & 15;
    int tid = threadIdx.x;

    __shared__ __align__(16) float s_q[HDIM];
    __shared__ __align__(16) float sm_acc[32][HDIM];
    __shared__ float sm_l[32];

    if (tid < HDIM) {
        int d = tid;
        const float* qb = g_proj + b * DMODEL + h * HDIM;
        float qv = qb[d];
        float qr;
        if (d < ROT) {
            float qp = qb[d ^ 1];
            float invf = __powf(10000.f, -(float)(d >> 1) / 16.f);
            float sn, cs;
            sincosf(4096.f * invf, &sn, &cs);
            qr = (d & 1) ? qv * cs + qp * sn : qv * cs - qp * sn;
        } else {
            qr = qv;
        }
        s_q[d] = qr;
    }
    __syncthreads();

    int lane = tid & 31, warp = tid >> 5;
    int g = lane >> 3, l8 = lane & 7;
    int gid = warp * 4 + g;

    float4 qA = *(const float4*)(s_q + l8 * 4);
    float4 qB = *(const float4*)(s_q + 32 + l8 * 4);

    float invf0 = __powf(10000.f, -(float)(2 * l8) / 16.f);
    float invf1 = __powf(10000.f, -(float)(2 * l8 + 1) / 16.f);

    int i0 = split * CHUNK + warp * 4 + g;
    float s0, c0, s1, c1, sd0, cd0, sd1, cd1;
    sincosf((float)i0 * invf0, &s0, &c0);
    sincosf((float)i0 * invf1, &s1, &c1);
    sincosf(32.f * invf0, &sd0, &cd0);
    sincosf(32.f * invf1, &sd1, &cd1);

    const float4* kbase = (const float4*)(kc + (size_t)(b * NHEADS + h) * CACHE * HDIM);
    const float4* vbase = (const float4*)(vc + (size_t)(b * NHEADS + h) * CACHE * HDIM);

    float l = 0.f;
    float4 accA = make_float4(0.f, 0.f, 0.f, 0.f);
    float4 accB = make_float4(0.f, 0.f, 0.f, 0.f);

#pragma unroll 4
    for (int it = 0; it < CHUNK / 32; it++) {
        size_t row = (size_t)(i0 + it * 32) * (HDIM / 4);
        float4 kA = __ldcs(kbase + row + l8);
        float4 kB = __ldcs(kbase + row + 8 + l8);
        float4 vA = __ldcs(vbase + row + l8);
        float4 vB = __ldcs(vbase + row + 8 + l8);

        {
            float x0 = kA.x, x1 = kA.y, x2 = kA.z, x3 = kA.w;
            kA.x = x0 * c0 - x1 * s0;  kA.y = x1 * c0 + x0 * s0;
            kA.z = x2 * c1 - x3 * s1;  kA.w = x3 * c1 + x2 * s1;
        }
        {
            float t0 = c0 * cd0 - s0 * sd0;  s0 = s0 * cd0 + c0 * sd0;  c0 = t0;
            float t1 = c1 * cd1 - s1 * sd1;  s1 = s1 * cd1 + c1 * sd1;  c1 = t1;
        }

        float p = kA.x * qA.x;
        p = fmaf(kA.y, qA.y, p);  p = fmaf(kA.z, qA.z, p);  p = fmaf(kA.w, qA.w, p);
        p = fmaf(kB.x, qB.x, p);  p = fmaf(kB.y, qB.y, p);
        p = fmaf(kB.z, qB.z, p);  p = fmaf(kB.w, qB.w, p);
        p += __shfl_xor_sync(0xffffffffu, p, 1);
        p += __shfl_xor_sync(0xffffffffu, p, 2);
        p += __shfl_xor_sync(0xffffffffu, p, 4);

        float w = __expf(p * 0.125f);
        l += w;
        accA.x = fmaf(w, vA.x, accA.x);  accA.y = fmaf(w, vA.y, accA.y);
        accA.z = fmaf(w, vA.z, accA.z);  accA.w = fmaf(w, vA.w, accA.w);
        accB.x = fmaf(w, vB.x, accB.x);  accB.y = fmaf(w, vB.y, accB.y);
        accB.z = fmaf(w, vB.z, accB.z);  accB.w = fmaf(w, vB.w, accB.w);
    }

    *(float4*)(&sm_acc[gid][l8 * 4])      = accA;
    *(float4*)(&sm_acc[gid][32 + l8 * 4]) = accB;
    if (l8 == 0) sm_l[gid] = l;
    __syncthreads();

    if (tid < HDIM) {
        int d = tid;
        float num = 0.f;
#pragma unroll
        for (int g2 = 0; g2 < 32; g2++) num += sm_acc[g2][d];
        int idx = pair * SPLITS + split;
        g_pacc[idx * HDIM + d] = num;
        if (d == 0) {
            float L = 0.f;
#pragma unroll
            for (int g2 = 0; g2 < 32; g2++) L += sm_l[g2];
            g_pl[idx] = L;
        }
    }
}

// ---------------------------------------------------------------------------
// Kernel 3: combine — latency-optimized.  All global loads issued up front
// (8 g_pl + 8 g_pacc + q/k/v slices, MLP~19); new-token score reduced with
// warp shfl + single 2-element smem exchange (1 sync, not 6).
// ---------------------------------------------------------------------------
__global__ void combine_kernel() {
    int pair = blockIdx.x;
    int b = pair >> 4, h = pair & 15;
    int d = threadIdx.x;          // 0..63
    int warp = d >> 5;

    __shared__ float swsum[2];

    const float* qb = g_proj + (0 * BS + b) * DMODEL + h * HDIM;
    const float* kb = g_proj + (1 * BS + b) * DMODEL + h * HDIM;
    const float* vb = g_proj + (2 * BS + b) * DMODEL + h * HDIM;

    // ---- issue every global load up front ----
    float pl[SPLITS], pacc[SPLITS];
#pragma unroll
    for (int s = 0; s < SPLITS; s++) pl[s] = g_pl[pair * SPLITS + s];
#pragma unroll
    for (int s = 0; s < SPLITS; s++) pacc[s] = g_pacc[(pair * SPLITS + s) * HDIM + d];
    float qv = qb[d], kv = kb[d], vv = vb[d];
    float qp = 0.f, kp = 0.f;
    if (d < ROT) { qp = qb[d ^ 1]; kp = kb[d ^ 1]; }

    // ---- rope on q,k for new token ----
    float qr, kr;
    if (d < ROT) {
        float invf = __powf(10000.f, -(float)(d >> 1) / 16.f);
        float sn, cs;
        sincosf(4096.f * invf, &sn, &cs);
        if (d & 1) { qr = qv * cs + qp * sn; kr = kv * cs + kp * sn; }
        else       { qr = qv * cs - qp * sn; kr = kv * cs - kp * sn; }
    } else { qr = qv; kr = kv; }

    // ---- 64-wide dot via shfl + one smem exchange ----
    float r = qr * kr;
    r += __shfl_xor_sync(0xffffffffu, r, 16);
    r += __shfl_xor_sync(0xffffffffu, r, 8);
    r += __shfl_xor_sync(0xffffffffu, r, 4);
    r += __shfl_xor_sync(0xffffffffu, r, 2);
    r += __shfl_xor_sync(0xffffffffu, r, 1);
    if ((d & 31) == 0) swsum[warp] = r;
    __syncthreads();
    float snew = (swsum[0] + swsum[1]) * 0.125f;

    float en  = __expf(snew);
    float L   = en;
    float num = en * vv;
#pragma unroll
    for (int s = 0; s < SPLITS; s++) { L += pl[s]; num += pacc[s]; }

    g_attn[b * DMODEL + h * HDIM + d] = num / L;
}

// ---------------------------------------------------------------------------
// Kernel 4: output projection.
// ---------------------------------------------------------------------------
__global__ void __launch_bounds__(1024, 1)
oproj_kernel(const float* __restrict__ WO,
             const float* __restrict__ bO,
             float* __restrict__ out) {
    gemv_block(g_attn, WO, bO, out, blockIdx.x * 8);
}

// ---------------------------------------------------------------------------
extern "C" void kernel_launch(void* const* d_in, const int* in_sizes, int n_in,
                              void* d_out, int out_size) {
    const float* q  = (const float*)d_in[0];
    const float* kc = (const float*)d_in[1];
    const float* vc = (const float*)d_in[2];
    const float* WQ = (const float*)d_in[3];
    const float* bQ = (const float*)d_in[4];
    const float* WK = (const float*)d_in[5];
    const float* bK = (const float*)d_in[6];
    const float* WV = (const float*)d_in[7];
    const float* bV = (const float*)d_in[8];
    const float* WO = (const float*)d_in[9];
    const float* bO = (const float*)d_in[10];

    proj_kernel<<<384, 1024>>>(q, WQ, bQ, WK, bK, WV, bV);
    attn_kernel<<<dim3(SPLITS, NPAIRS), 256>>>(kc, vc);
    combine_kernel<<<NPAIRS, HDIM>>>();
    oproj_kernel<<<DMODEL / 8, 1024>>>(WO, bO, (float*)d_out);
}

// round 12
// speedup vs baseline: 1.0341x; 1.0341x over previous
#include <cuda_runtime.h>
#include <math.h>

#define NHEADS   16
#define HDIM     64
#define ROT      32
#define BS       8
#define CACHE    4096
#define DMODEL   1024
#define SPLITS   8
#define CHUNK    (CACHE / SPLITS)   // 512
#define NPAIRS   (BS * NHEADS)      // 128

// Scratch (device globals — no runtime allocation allowed)
__device__ float g_proj[3 * BS * DMODEL];            // qh, kh, vh (proj + bias)
__device__ float g_pl[NPAIRS * SPLITS];              // split partial sum-of-exp
__device__ float g_pacc[NPAIRS * SPLITS * HDIM];     // split partial weighted V
__device__ float g_attn[BS * DMODEL];
__device__ float g_sink;                             // DCE sink; never written

// ---------------------------------------------------------------------------
// GEMV core (R7 config — best measured): 512 threads = 16 warps; 2 warps per
// output column.  Weight loads issued first, staging overlaps, shfl tree,
// 2-partial smem combine.  launch_bounds(512,2) caps regs at 64 so two
// blocks co-reside per SM.
// ---------------------------------------------------------------------------
__device__ __forceinline__ void gemv_block(
    const float* __restrict__ X,
    const float* __restrict__ W,
    const float* __restrict__ bias,
    float* __restrict__ Y,
    int obase)
{
    __shared__ __align__(16) float sx[BS * DMODEL];
    __shared__ float spart[16][BS];

    int tid  = threadIdx.x;
    int warp = tid >> 5, lane = tid & 31;
    int colw = warp >> 1, half = warp & 1;
    int o    = obase + colw;

    const float4* W4 = (const float4*)(W + (size_t)o * DMODEL);
    const float4* x4 = (const float4*)sx;

    // 1) weight loads first
    float4 wv[4];
#pragma unroll
    for (int it = 0; it < 4; it++) wv[it] = W4[half * 128 + lane + it * 32];

    // 2) staging loads overlap
    {
        const float4* g4 = (const float4*)X;
        float4* s4 = (float4*)sx;
        float4 st[4];
#pragma unroll
        for (int it = 0; it < 4; it++) st[it] = g4[tid + it * 512];
#pragma unroll
        for (int it = 0; it < 4; it++) s4[tid + it * 512] = st[it];
    }
    __syncthreads();

    float acc[BS];
#pragma unroll
    for (int b = 0; b < BS; b++) acc[b] = 0.f;
#pragma unroll
    for (int it = 0; it < 4; it++) {
        int d4 = half * 128 + lane + it * 32;
#pragma unroll
        for (int b = 0; b < BS; b++) {
            float4 xv = x4[b * (DMODEL / 4) + d4];
            acc[b] += wv[it].x * xv.x + wv[it].y * xv.y + wv[it].z * xv.z + wv[it].w * xv.w;
        }
    }
#pragma unroll
    for (int off = 16; off; off >>= 1) {
#pragma unroll
        for (int b = 0; b < BS; b++)
            acc[b] += __shfl_xor_sync(0xffffffffu, acc[b], off);
    }
    if (lane == 0) {
#pragma unroll
        for (int b = 0; b < BS; b++) spart[warp][b] = acc[b];
    }
    __syncthreads();

    if (tid < 64) {
        int c = tid >> 3, b = tid & 7;
        int oc = obase + c;
        float v = spart[2 * c][b] + spart[2 * c + 1][b] + bias[oc];
        Y[b * DMODEL + oc] = v;
    }
}

// ---------------------------------------------------------------------------
// Kernel 1: fused QKV projection.  grid 384 x 512thr; 8 cols/block.
// ---------------------------------------------------------------------------
__global__ void __launch_bounds__(512, 2)
proj_kernel(const float* __restrict__ q,
            const float* __restrict__ WQ, const float* __restrict__ bQ,
            const float* __restrict__ WK, const float* __restrict__ bK,
            const float* __restrict__ WV, const float* __restrict__ bV) {
    int w0 = blockIdx.x * 8;
    int p  = w0 >> 10;
    int o  = w0 & 1023;
    const float* W    = (p == 0) ? WQ : (p == 1) ? WK : WV;
    const float* bias = (p == 0) ? bQ : (p == 1) ? bK : bV;
    gemv_block(q, W, bias, g_proj + (size_t)p * BS * DMODEL, o);
}

// ---------------------------------------------------------------------------
// Kernel 2: flash-decode, split-K.  grid (SPLITS+1, 128): planes 0..7 do
// attention; plane 8 warms WO in L2 with plain loads (no inline asm) so
// oproj hits L2.  K/V use __ldcs (evict-first) so WO lines survive.
// ---------------------------------------------------------------------------
__global__ void attn_kernel(const float* __restrict__ kc,
                            const float* __restrict__ vc,
                            const float* __restrict__ WO) {
    int split = blockIdx.x;
    int pair  = blockIdx.y;
    int tid = threadIdx.x;

    if (split == SPLITS) {
        // ---- WO warm plane: block 'pair' covers 8 rows (8192 floats) ----
        const float4* w4 = (const float4*)WO + (size_t)pair * 2048;
        float s = 0.f;
#pragma unroll
        for (int i = 0; i < 8; i++) {
            float4 v = w4[tid + i * 256];     // 256 thr * 8 = 2048 float4
            s += v.x + v.y + v.z + v.w;
        }
        if (s == 1.2345678e33f) g_sink = s;   // defeat DCE; never taken
        return;
    }

    int b = pair >> 4, h = pair & 15;

    __shared__ __align__(16) float s_q[HDIM];
    __shared__ __align__(16) float sm_acc[32][HDIM];
    __shared__ float sm_l[32];

    if (tid < HDIM) {
        int d = tid;
        const float* qb = g_proj + b * DMODEL + h * HDIM;
        float qv = qb[d];
        float qr;
        if (d < ROT) {
            float qp = qb[d ^ 1];
            float invf = __powf(10000.f, -(float)(d >> 1) / 16.f);
            float sn, cs;
            sincosf(4096.f * invf, &sn, &cs);
            qr = (d & 1) ? qv * cs + qp * sn : qv * cs - qp * sn;
        } else {
            qr = qv;
        }
        s_q[d] = qr;
    }
    __syncthreads();

    int lane = tid & 31, warp = tid >> 5;
    int g = lane >> 3, l8 = lane & 7;
    int gid = warp * 4 + g;

    float4 qA = *(const float4*)(s_q + l8 * 4);
    float4 qB = *(const float4*)(s_q + 32 + l8 * 4);

    float invf0 = __powf(10000.f, -(float)(2 * l8) / 16.f);
    float invf1 = __powf(10000.f, -(float)(2 * l8 + 1) / 16.f);

    int i0 = split * CHUNK + warp * 4 + g;
    float s0, c0, s1, c1, sd0, cd0, sd1, cd1;
    sincosf((float)i0 * invf0, &s0, &c0);
    sincosf((float)i0 * invf1, &s1, &c1);
    sincosf(32.f * invf0, &sd0, &cd0);
    sincosf(32.f * invf1, &sd1, &cd1);

    const float4* kbase = (const float4*)(kc + (size_t)(b * NHEADS + h) * CACHE * HDIM);
    const float4* vbase = (const float4*)(vc + (size_t)(b * NHEADS + h) * CACHE * HDIM);

    float l = 0.f;
    float4 accA = make_float4(0.f, 0.f, 0.f, 0.f);
    float4 accB = make_float4(0.f, 0.f, 0.f, 0.f);

#pragma unroll 4
    for (int it = 0; it < CHUNK / 32; it++) {
        size_t row = (size_t)(i0 + it * 32) * (HDIM / 4);
        float4 kA = __ldcs(kbase + row + l8);
        float4 kB = __ldcs(kbase + row + 8 + l8);
        float4 vA = __ldcs(vbase + row + l8);
        float4 vB = __ldcs(vbase + row + 8 + l8);

        {
            float x0 = kA.x, x1 = kA.y, x2 = kA.z, x3 = kA.w;
            kA.x = x0 * c0 - x1 * s0;  kA.y = x1 * c0 + x0 * s0;
            kA.z = x2 * c1 - x3 * s1;  kA.w = x3 * c1 + x2 * s1;
        }
        {
            float t0 = c0 * cd0 - s0 * sd0;  s0 = s0 * cd0 + c0 * sd0;  c0 = t0;
            float t1 = c1 * cd1 - s1 * sd1;  s1 = s1 * cd1 + c1 * sd1;  c1 = t1;
        }

        float p = kA.x * qA.x;
        p = fmaf(kA.y, qA.y, p);  p = fmaf(kA.z, qA.z, p);  p = fmaf(kA.w, qA.w, p);
        p = fmaf(kB.x, qB.x, p);  p = fmaf(kB.y, qB.y, p);
        p = fmaf(kB.z, qB.z, p);  p = fmaf(kB.w, qB.w, p);
        p += __shfl_xor_sync(0xffffffffu, p, 1);
        p += __shfl_xor_sync(0xffffffffu, p, 2);
        p += __shfl_xor_sync(0xffffffffu, p, 4);

        float w = __expf(p * 0.125f);
        l += w;
        accA.x = fmaf(w, vA.x, accA.x);  accA.y = fmaf(w, vA.y, accA.y);
        accA.z = fmaf(w, vA.z, accA.z);  accA.w = fmaf(w, vA.w, accA.w);
        accB.x = fmaf(w, vB.x, accB.x);  accB.y = fmaf(w, vB.y, accB.y);
        accB.w = fmaf(w, vB.w, accB.w);  accB.z = fmaf(w, vB.z, accB.z);
    }

    *(float4*)(&sm_acc[gid][l8 * 4])      = accA;
    *(float4*)(&sm_acc[gid][32 + l8 * 4]) = accB;
    if (l8 == 0) sm_l[gid] = l;
    __syncthreads();

    if (tid < HDIM) {
        int d = tid;
        float num = 0.f;
#pragma unroll
        for (int g2 = 0; g2 < 32; g2++) num += sm_acc[g2][d];
        int idx = pair * SPLITS + split;
        g_pacc[idx * HDIM + d] = num;
        if (d == 0) {
            float L = 0.f;
#pragma unroll
            for (int g2 = 0; g2 < 32; g2++) L += sm_l[g2];
            g_pl[idx] = L;
        }
    }
}

// ---------------------------------------------------------------------------
// Kernel 3: combine — batched loads up front, single smem exchange.
// ---------------------------------------------------------------------------
__global__ void combine_kernel() {
    int pair = blockIdx.x;
    int b = pair >> 4, h = pair & 15;
    int d = threadIdx.x;          // 0..63
    int warp = d >> 5;

    __shared__ float swsum[2];

    const float* qb = g_proj + (0 * BS + b) * DMODEL + h * HDIM;
    const float* kb = g_proj + (1 * BS + b) * DMODEL + h * HDIM;
    const float* vb = g_proj + (2 * BS + b) * DMODEL + h * HDIM;

    float pl[SPLITS], pacc[SPLITS];
#pragma unroll
    for (int s = 0; s < SPLITS; s++) pl[s] = g_pl[pair * SPLITS + s];
#pragma unroll
    for (int s = 0; s < SPLITS; s++) pacc[s] = g_pacc[(pair * SPLITS + s) * HDIM + d];
    float qv = qb[d], kv = kb[d], vv = vb[d];
    float qp = 0.f, kp = 0.f;
    if (d < ROT) { qp = qb[d ^ 1]; kp = kb[d ^ 1]; }

    float qr, kr;
    if (d < ROT) {
        float invf = __powf(10000.f, -(float)(d >> 1) / 16.f);
        float sn, cs;
        sincosf(4096.f * invf, &sn, &cs);
        if (d & 1) { qr = qv * cs + qp * sn; kr = kv * cs + kp * sn; }
        else       { qr = qv * cs - qp * sn; kr = kv * cs - kp * sn; }
    } else { qr = qv; kr = kv; }

    float r = qr * kr;
    r += __shfl_xor_sync(0xffffffffu, r, 16);
    r += __shfl_xor_sync(0xffffffffu, r, 8);
    r += __shfl_xor_sync(0xffffffffu, r, 4);
    r += __shfl_xor_sync(0xffffffffu, r, 2);
    r += __shfl_xor_sync(0xffffffffu, r, 1);
    if ((d & 31) == 0) swsum[warp] = r;
    __syncthreads();
    float snew = (swsum[0] + swsum[1]) * 0.125f;

    float en  = __expf(snew);
    float L   = en;
    float num = en * vv;
#pragma unroll
    for (int s = 0; s < SPLITS; s++) { L += pl[s]; num += pacc[s]; }

    g_attn[b * DMODEL + h * HDIM + d] = num / L;
}

// ---------------------------------------------------------------------------
// Kernel 4: output projection (reads WO from warmed L2).
// ---------------------------------------------------------------------------
__global__ void __launch_bounds__(512, 2)
oproj_kernel(const float* __restrict__ WO,
             const float* __restrict__ bO,
             float* __restrict__ out) {
    gemv_block(g_attn, WO, bO, out, blockIdx.x * 8);
}

// ---------------------------------------------------------------------------
extern "C" void kernel_launch(void* const* d_in, const int* in_sizes, int n_in,
                              void* d_out, int out_size) {
    const float* q  = (const float*)d_in[0];
    const float* kc = (const float*)d_in[1];
    const float* vc = (const float*)d_in[2];
    const float* WQ = (const float*)d_in[3];
    const float* bQ = (const float*)d_in[4];
    const float* WK = (const float*)d_in[5];
    const float* bK = (const float*)d_in[6];
    const float* WV = (const float*)d_in[7];
    const float* bV = (const float*)d_in[8];
    const float* WO = (const float*)d_in[9];
    const float* bO = (const float*)d_in[10];

    proj_kernel<<<384, 512>>>(q, WQ, bQ, WK, bK, WV, bV);
    attn_kernel<<<dim3(SPLITS + 1, NPAIRS), 256>>>(kc, vc, WO);
    combine_kernel<<<NPAIRS, HDIM>>>();
    oproj_kernel<<<DMODEL / 8, 512>>>(WO, bO, (float*)d_out);
}

// round 13
// speedup vs baseline: 1.0429x; 1.0086x over previous
#include <cuda_runtime.h>
#include <math.h>

#define NHEADS   16
#define HDIM     64
#define ROT      32
#define BS       8
#define CACHE    4096
#define DMODEL   1024
#define SPLITS   4
#define CHUNK    (CACHE / SPLITS)   // 1024
#define NPAIRS   (BS * NHEADS)      // 128

// Scratch (device globals — no runtime allocation allowed)
__device__ float g_proj[3 * BS * DMODEL];            // qh, kh, vh (proj + bias)
__device__ float g_pl[NPAIRS * SPLITS];              // split partial sum-of-exp
__device__ float g_pacc[NPAIRS * SPLITS * HDIM];     // split partial weighted V
__device__ float g_attn[BS * DMODEL];
__device__ float g_sink;                             // DCE sink; never written

// ---------------------------------------------------------------------------
// Kernel 1: fused QKV projection (R12 config — measured ~4us).
// 512 threads, 8 cols/block, 2 warps/col, weights-before-staging.
// ---------------------------------------------------------------------------
__global__ void __launch_bounds__(512, 2)
proj_kernel(const float* __restrict__ q,
            const float* __restrict__ WQ, const float* __restrict__ bQ,
            const float* __restrict__ WK, const float* __restrict__ bK,
            const float* __restrict__ WV, const float* __restrict__ bV) {
    __shared__ __align__(16) float sx[BS * DMODEL];
    __shared__ float spart[16][BS];

    int w0 = blockIdx.x * 8;
    int p  = w0 >> 10;
    int o0 = w0 & 1023;
    const float* W    = (p == 0) ? WQ : (p == 1) ? WK : WV;
    const float* bias = (p == 0) ? bQ : (p == 1) ? bK : bV;
    float* Y = g_proj + (size_t)p * BS * DMODEL;

    int tid  = threadIdx.x;
    int warp = tid >> 5, lane = tid & 31;
    int colw = warp >> 1, half = warp & 1;
    int o    = o0 + colw;

    const float4* W4 = (const float4*)(W + (size_t)o * DMODEL);
    const float4* x4 = (const float4*)sx;

    float4 wv[4];
#pragma unroll
    for (int it = 0; it < 4; it++) wv[it] = W4[half * 128 + lane + it * 32];

    {
        const float4* g4 = (const float4*)q;
        float4* s4 = (float4*)sx;
        float4 st[4];
#pragma unroll
        for (int it = 0; it < 4; it++) st[it] = g4[tid + it * 512];
#pragma unroll
        for (int it = 0; it < 4; it++) s4[tid + it * 512] = st[it];
    }
    __syncthreads();

    float acc[BS];
#pragma unroll
    for (int b = 0; b < BS; b++) acc[b] = 0.f;
#pragma unroll
    for (int it = 0; it < 4; it++) {
        int d4 = half * 128 + lane + it * 32;
#pragma unroll
        for (int b = 0; b < BS; b++) {
            float4 xv = x4[b * (DMODEL / 4) + d4];
            acc[b] += wv[it].x * xv.x + wv[it].y * xv.y + wv[it].z * xv.z + wv[it].w * xv.w;
        }
    }
#pragma unroll
    for (int off = 16; off; off >>= 1) {
#pragma unroll
        for (int b = 0; b < BS; b++)
            acc[b] += __shfl_xor_sync(0xffffffffu, acc[b], off);
    }
    if (lane == 0) {
#pragma unroll
        for (int b = 0; b < BS; b++) spart[warp][b] = acc[b];
    }
    __syncthreads();

    if (tid < 64) {
        int c = tid >> 3, b = tid & 7;
        int oc = o0 + c;
        Y[b * DMODEL + oc] = spart[2 * c][b] + spart[2 * c + 1][b] + bias[oc];
    }
}

// ---------------------------------------------------------------------------
// Kernel 2: flash-decode, split-K=4.  grid (4, 128) = 512 blocks x 256thr
// (~0.9 waves at 4 blocks/SM — single wave).  8 lanes/key, 4 keys/warp-iter,
// no online max, incremental rope.  Each block ends by reading its distinct
// 8KB slice of WO -> WO is L2-resident right before oproj.
// ---------------------------------------------------------------------------
__global__ void __launch_bounds__(256)
attn_kernel(const float* __restrict__ kc,
            const float* __restrict__ vc,
            const float* __restrict__ WO) {
    int split = blockIdx.x;
    int pair  = blockIdx.y;
    int b = pair >> 4, h = pair & 15;
    int tid = threadIdx.x;

    __shared__ __align__(16) float s_q[HDIM];
    __shared__ __align__(16) float sm_acc[32][HDIM];
    __shared__ float sm_l[32];

    if (tid < HDIM) {
        int d = tid;
        const float* qb = g_proj + b * DMODEL + h * HDIM;
        float qv = qb[d];
        float qr;
        if (d < ROT) {
            float qp = qb[d ^ 1];
            float invf = __powf(10000.f, -(float)(d >> 1) / 16.f);
            float sn, cs;
            sincosf(4096.f * invf, &sn, &cs);
            qr = (d & 1) ? qv * cs + qp * sn : qv * cs - qp * sn;
        } else {
            qr = qv;
        }
        s_q[d] = qr;
    }
    __syncthreads();

    int lane = tid & 31, warp = tid >> 5;
    int g = lane >> 3, l8 = lane & 7;
    int gid = warp * 4 + g;

    float4 qA = *(const float4*)(s_q + l8 * 4);
    float4 qB = *(const float4*)(s_q + 32 + l8 * 4);

    float invf0 = __powf(10000.f, -(float)(2 * l8) / 16.f);
    float invf1 = __powf(10000.f, -(float)(2 * l8 + 1) / 16.f);

    int i0 = split * CHUNK + warp * 4 + g;
    float s0, c0, s1, c1, sd0, cd0, sd1, cd1;
    sincosf((float)i0 * invf0, &s0, &c0);
    sincosf((float)i0 * invf1, &s1, &c1);
    sincosf(32.f * invf0, &sd0, &cd0);
    sincosf(32.f * invf1, &sd1, &cd1);

    const float4* kbase = (const float4*)(kc + (size_t)(b * NHEADS + h) * CACHE * HDIM);
    const float4* vbase = (const float4*)(vc + (size_t)(b * NHEADS + h) * CACHE * HDIM);

    float l = 0.f;
    float4 accA = make_float4(0.f, 0.f, 0.f, 0.f);
    float4 accB = make_float4(0.f, 0.f, 0.f, 0.f);

#pragma unroll 4
    for (int it = 0; it < CHUNK / 32; it++) {
        size_t row = (size_t)(i0 + it * 32) * (HDIM / 4);
        float4 kA = __ldcs(kbase + row + l8);
        float4 kB = __ldcs(kbase + row + 8 + l8);
        float4 vA = __ldcs(vbase + row + l8);
        float4 vB = __ldcs(vbase + row + 8 + l8);

        {
            float x0 = kA.x, x1 = kA.y, x2 = kA.z, x3 = kA.w;
            kA.x = x0 * c0 - x1 * s0;  kA.y = x1 * c0 + x0 * s0;
            kA.z = x2 * c1 - x3 * s1;  kA.w = x3 * c1 + x2 * s1;
        }
        {
            float t0 = c0 * cd0 - s0 * sd0;  s0 = s0 * cd0 + c0 * sd0;  c0 = t0;
            float t1 = c1 * cd1 - s1 * sd1;  s1 = s1 * cd1 + c1 * sd1;  c1 = t1;
        }

        float p = kA.x * qA.x;
        p = fmaf(kA.y, qA.y, p);  p = fmaf(kA.z, qA.z, p);  p = fmaf(kA.w, qA.w, p);
        p = fmaf(kB.x, qB.x, p);  p = fmaf(kB.y, qB.y, p);
        p = fmaf(kB.z, qB.z, p);  p = fmaf(kB.w, qB.w, p);
        p += __shfl_xor_sync(0xffffffffu, p, 1);
        p += __shfl_xor_sync(0xffffffffu, p, 2);
        p += __shfl_xor_sync(0xffffffffu, p, 4);

        float w = __expf(p * 0.125f);
        l += w;
        accA.x = fmaf(w, vA.x, accA.x);  accA.y = fmaf(w, vA.y, accA.y);
        accA.z = fmaf(w, vA.z, accA.z);  accA.w = fmaf(w, vA.w, accA.w);
        accB.x = fmaf(w, vB.x, accB.x);  accB.y = fmaf(w, vB.y, accB.y);
        accB.z = fmaf(w, vB.z, accB.z);  accB.w = fmaf(w, vB.w, accB.w);
    }

    *(float4*)(&sm_acc[gid][l8 * 4])      = accA;
    *(float4*)(&sm_acc[gid][32 + l8 * 4]) = accB;
    if (l8 == 0) sm_l[gid] = l;
    __syncthreads();

    if (tid < HDIM) {
        int d = tid;
        float num = 0.f;
#pragma unroll
        for (int g2 = 0; g2 < 32; g2++) num += sm_acc[g2][d];
        int idx = pair * SPLITS + split;
        g_pacc[idx * HDIM + d] = num;
        if (d == 0) {
            float L = 0.f;
#pragma unroll
            for (int g2 = 0; g2 < 32; g2++) L += sm_l[g2];
            g_pl[idx] = L;
        }
    }

    // ---- late WO warm: this block's distinct 8KB slice (512 blocks x 8KB
    // = 4MB).  Runs at the END of each block -> survives until oproj. ----
    {
        int blk = split * NPAIRS + pair;                 // 0..511
        const float4* w4 = (const float4*)WO + (size_t)blk * 512;
        float4 a = w4[tid];
        float4 c = w4[tid + 256];
        float s = a.x + a.y + a.z + a.w + c.x + c.y + c.z + c.w;
        if (s == 1.2345678e33f) g_sink = s;              // defeat DCE; never taken
    }
}

// ---------------------------------------------------------------------------
// Kernel 3: combine — batched loads up front, single smem exchange.
// ---------------------------------------------------------------------------
__global__ void combine_kernel() {
    int pair = blockIdx.x;
    int b = pair >> 4, h = pair & 15;
    int d = threadIdx.x;          // 0..63
    int warp = d >> 5;

    __shared__ float swsum[2];

    const float* qb = g_proj + (0 * BS + b) * DMODEL + h * HDIM;
    const float* kb = g_proj + (1 * BS + b) * DMODEL + h * HDIM;
    const float* vb = g_proj + (2 * BS + b) * DMODEL + h * HDIM;

    float pl[SPLITS], pacc[SPLITS];
#pragma unroll
    for (int s = 0; s < SPLITS; s++) pl[s] = g_pl[pair * SPLITS + s];
#pragma unroll
    for (int s = 0; s < SPLITS; s++) pacc[s] = g_pacc[(pair * SPLITS + s) * HDIM + d];
    float qv = qb[d], kv = kb[d], vv = vb[d];
    float qp = 0.f, kp = 0.f;
    if (d < ROT) { qp = qb[d ^ 1]; kp = kb[d ^ 1]; }

    float qr, kr;
    if (d < ROT) {
        float invf = __powf(10000.f, -(float)(d >> 1) / 16.f);
        float sn, cs;
        sincosf(4096.f * invf, &sn, &cs);
        if (d & 1) { qr = qv * cs + qp * sn; kr = kv * cs + kp * sn; }
        else       { qr = qv * cs - qp * sn; kr = kv * cs - kp * sn; }
    } else { qr = qv; kr = kv; }

    float r = qr * kr;
    r += __shfl_xor_sync(0xffffffffu, r, 16);
    r += __shfl_xor_sync(0xffffffffu, r, 8);
    r += __shfl_xor_sync(0xffffffffu, r, 4);
    r += __shfl_xor_sync(0xffffffffu, r, 2);
    r += __shfl_xor_sync(0xffffffffu, r, 1);
    if ((d & 31) == 0) swsum[warp] = r;
    __syncthreads();
    float snew = (swsum[0] + swsum[1]) * 0.125f;

    float en  = __expf(snew);
    float L   = en;
    float num = en * vv;
#pragma unroll
    for (int s = 0; s < SPLITS; s++) { L += pl[s]; num += pacc[s]; }

    g_attn[b * DMODEL + h * HDIM + d] = num / L;
}

// ---------------------------------------------------------------------------
// Kernel 4: output projection.  256 blocks x 512thr, 4 cols/block (4 warps
// per column): >1 block/SM so staging rounds overlap across blocks, and
// half the per-block weight-load chain.  WO is L2-hot from attn's tail.
// ---------------------------------------------------------------------------
__global__ void __launch_bounds__(512, 2)
oproj_kernel(const float* __restrict__ WO,
             const float* __restrict__ bO,
             float* __restrict__ out) {
    __shared__ __align__(16) float sx[BS * DMODEL];
    __shared__ float spart[16][BS];

    int tid  = threadIdx.x;
    int warp = tid >> 5, lane = tid & 31;
    int colw = warp >> 2, quar = warp & 3;   // 4 cols/block, 4 warps/col
    int o    = blockIdx.x * 4 + colw;

    const float4* W4 = (const float4*)(WO + (size_t)o * DMODEL);
    const float4* x4 = (const float4*)sx;

    // weights first (quarter-dot: 2 float4/thread)
    float4 wv[2];
    wv[0] = W4[quar * 64 + lane];
    wv[1] = W4[quar * 64 + 32 + lane];

    // staging overlap
    {
        const float4* g4 = (const float4*)g_attn;
        float4* s4 = (float4*)sx;
        float4 st[4];
#pragma unroll
        for (int it = 0; it < 4; it++) st[it] = g4[tid + it * 512];
#pragma unroll
        for (int it = 0; it < 4; it++) s4[tid + it * 512] = st[it];
    }
    __syncthreads();

    float acc[BS];
#pragma unroll
    for (int b = 0; b < BS; b++) acc[b] = 0.f;
#pragma unroll
    for (int it = 0; it < 2; it++) {
        int d4 = quar * 64 + it * 32 + lane;
#pragma unroll
        for (int b = 0; b < BS; b++) {
            float4 xv = x4[b * (DMODEL / 4) + d4];
            acc[b] += wv[it].x * xv.x + wv[it].y * xv.y + wv[it].z * xv.z + wv[it].w * xv.w;
        }
    }
#pragma unroll
    for (int off = 16; off; off >>= 1) {
#pragma unroll
        for (int b = 0; b < BS; b++)
            acc[b] += __shfl_xor_sync(0xffffffffu, acc[b], off);
    }
    if (lane == 0) {
#pragma unroll
        for (int b = 0; b < BS; b++) spart[warp][b] = acc[b];
    }
    __syncthreads();

    if (tid < 32) {
        int c = tid >> 3, b = tid & 7;     // 4 cols x 8 batches
        int oc = blockIdx.x * 4 + c;
        float v = spart[4 * c][b] + spart[4 * c + 1][b]
                + spart[4 * c + 2][b] + spart[4 * c + 3][b] + bO[oc];
        out[b * DMODEL + oc] = v;
    }
}

// ---------------------------------------------------------------------------
extern "C" void kernel_launch(void* const* d_in, const int* in_sizes, int n_in,
                              void* d_out, int out_size) {
    const float* q  = (const float*)d_in[0];
    const float* kc = (const float*)d_in[1];
    const float* vc = (const float*)d_in[2];
    const float* WQ = (const float*)d_in[3];
    const float* bQ = (const float*)d_in[4];
    const float* WK = (const float*)d_in[5];
    const float* bK = (const float*)d_in[6];
    const float* WV = (const float*)d_in[7];
    const float* bV = (const float*)d_in[8];
    const float* WO = (const float*)d_in[9];
    const float* bO = (const float*)d_in[10];

    proj_kernel<<<384, 512>>>(q, WQ, bQ, WK, bK, WV, bV);
    attn_kernel<<<dim3(SPLITS, NPAIRS), 256>>>(kc, vc, WO);
    combine_kernel<<<NPAIRS, HDIM>>>();
    oproj_kernel<<<DMODEL / 4, 512>>>(WO, bO, (float*)d_out);
}